// round 1
// baseline (speedup 1.0000x reference)
#include <cuda_runtime.h>

#define N_ 2
#define C_ 64
#define D_ 8
#define H_ 56
#define W_ 56
#define G_ 8
#define K_ 27
#define CO_OFF 648
#define P_ (D_*H_*W_)          // 25088
#define DP_ (D_+2)
#define HP_ (H_+2)
#define WP_ (W_+2)
#define PPAD_ (DP_*HP_*WP_)    // 33640

// ---------------- scratch (no allocation allowed) ----------------
__device__ float g_xpad[N_*C_*PPAD_];    // padded input for offset conv
__device__ float g_y2pad[N_*C_*PPAD_];   // padded bn1+relu output for conv2
__device__ float g_off[N_*CO_OFF*P_];    // offset tensor (130 MB)
__device__ float g_y1[N_*C_*P_];         // deform conv output
__device__ float g_y3[N_*C_*P_];         // conv2 output
__device__ float g_stats[4*C_];          // mean1, istd1, mean2, istd2

// ---------------- kernel 0: build padded x, zero pad edges of y2pad ----------------
__global__ void padinit_kernel(const float* __restrict__ x) {
    int idx = blockIdx.x * 256 + threadIdx.x;
    if (idx >= N_*C_*PPAD_) return;
    int wp = idx % WP_;
    int hp = (idx / WP_) % HP_;
    int dp = (idx / (WP_*HP_)) % DP_;
    int nc = idx / PPAD_;
    bool interior = (dp >= 1 && dp <= D_ && hp >= 1 && hp <= H_ && wp >= 1 && wp <= W_);
    float v = 0.f;
    if (interior)
        v = x[nc * P_ + (dp-1) * (H_*W_) + (hp-1) * W_ + (wp-1)];
    g_xpad[idx] = v;
    if (!interior) g_y2pad[idx] = 0.f;
}

// ---------------- kernel 1: offset conv 64 -> 648, 3x3x3 ----------------
// grid: (N*D*H, 9)   block: (28, 8)   CO_TILE = 72 per blockIdx.y
__global__ __launch_bounds__(224) void offconv_kernel(const float* __restrict__ w_off,
                                                      const float* __restrict__ b_off) {
    int ndh = blockIdx.x;
    int h = ndh % H_;
    int d = (ndh / H_) % D_;
    int n = ndh / (D_*H_);
    int cot = blockIdx.y;               // 0..8
    int tx = threadIdx.x;               // 0..27 : w base
    int ty = threadIdx.y;               // 0..7
    int tid = ty * 28 + tx;

    __shared__ float xrow[58];
    __shared__ float wsm[72*3];

    float acc[9][2];
#pragma unroll
    for (int r = 0; r < 9; r++) { acc[r][0] = 0.f; acc[r][1] = 0.f; }

    const float* xp = g_xpad + n * (C_*PPAD_);

    for (int ci = 0; ci < C_; ci++) {
#pragma unroll
        for (int kd = 0; kd < 3; kd++) {
#pragma unroll
            for (int kh = 0; kh < 3; kh++) {
                const float* src = xp + ci * PPAD_ + (d + kd) * (HP_*WP_) + (h + kh) * WP_;
                if (tid < 58) xrow[tid] = src[tid];
                if (tid < 216) {
                    int co = tid / 3, kw = tid % 3;
                    wsm[tid] = w_off[(((cot*72 + co) * C_ + ci) * 27) + kd*9 + kh*3 + kw];
                }
                __syncthreads();
                float xa0 = xrow[tx],    xa1 = xrow[tx+1],  xa2 = xrow[tx+2];
                float xb0 = xrow[tx+28], xb1 = xrow[tx+29], xb2 = xrow[tx+30];
#pragma unroll
                for (int r = 0; r < 9; r++) {
                    int co = ty * 9 + r;
                    float v0 = wsm[co*3], v1 = wsm[co*3+1], v2 = wsm[co*3+2];
                    acc[r][0] += v0*xa0 + v1*xa1 + v2*xa2;
                    acc[r][1] += v0*xb0 + v1*xb1 + v2*xb2;
                }
                __syncthreads();
            }
        }
    }
#pragma unroll
    for (int r = 0; r < 9; r++) {
        int co = cot*72 + ty*9 + r;
        float b = b_off[co];
        int base = (n * CO_OFF + co) * P_ + (d * H_ + h) * W_;
        g_off[base + tx]      = acc[r][0] + b;
        g_off[base + tx + 28] = acc[r][1] + b;
    }
}

// ---------------- kernel 2: deformable conv (sample + GEMM) ----------------
// grid: N*D*H   block: (28, 8)
__global__ __launch_bounds__(224) void deform_kernel(const float* __restrict__ x,
                                                     const float* __restrict__ w1) {
    int ndh = blockIdx.x;
    int h = ndh % H_;
    int d = (ndh / H_) % D_;
    int n = ndh / (D_*H_);
    int tx = threadIdx.x;
    int ty = threadIdx.y;
    int tid = ty * 28 + tx;

    __shared__ float svals[8][56];
    __shared__ float wsm[64][9];     // padded stride 9 (bank conflicts)
    __shared__ int   clin[56][9];
    __shared__ float cwgt[56][9];

    float acc[8][2];
#pragma unroll
    for (int r = 0; r < 8; r++) { acc[r][0] = 0.f; acc[r][1] = 0.f; }

    const float* xn = x + n * (C_*P_);

    for (int g = 0; g < G_; g++) {
        for (int k = 0; k < K_; k++) {
            // --- corner index/weight computation: one thread per w position ---
            if (tid < 56) {
                int w = tid;
                int kd = k / 9, kh = (k / 3) % 3, kw = k % 3;
                int obase = (n * CO_OFF + (g*K_ + k) * 3) * P_ + (d * H_ + h) * W_ + w;
                float od = g_off[obase];
                float oh = g_off[obase + P_];
                float ow = g_off[obase + 2*P_];
                float pd = (float)(d + kd - 1) + od;
                float ph = (float)(h + kh - 1) + oh;
                float pw = (float)(w + kw - 1) + ow;
                float d0f = floorf(pd), h0f = floorf(ph), w0f = floorf(pw);
                float fd = pd - d0f, fh = ph - h0f, fw = pw - w0f;
                int d0 = (int)d0f, h0 = (int)h0f, w0 = (int)w0f;
#pragma unroll
                for (int c8 = 0; c8 < 8; c8++) {
                    int cd = c8 >> 2, ch = (c8 >> 1) & 1, cw = c8 & 1;
                    int id = d0 + cd, ih = h0 + ch, iw = w0 + cw;
                    float wt = (cd ? fd : 1.f - fd) * (ch ? fh : 1.f - fh) * (cw ? fw : 1.f - fw);
                    bool valid = (id >= 0 && id < D_ && ih >= 0 && ih < H_ && iw >= 0 && iw < W_);
                    int idc = min(max(id, 0), D_-1);
                    int ihc = min(max(ih, 0), H_-1);
                    int iwc = min(max(iw, 0), W_-1);
                    clin[w][c8] = (idc * H_ + ihc) * W_ + iwc;
                    cwgt[w][c8] = valid ? wt : 0.f;
                }
            }
            // --- load weight slice w1[o][g*8+cl][k] ---
            for (int i = tid; i < 512; i += 224) {
                int o = i >> 3, cl = i & 7;
                wsm[o][cl] = w1[(o * C_ + g*8 + cl) * K_ + k];
            }
            __syncthreads();
            // --- trilinear sampling: 448 values ---
            for (int i = tid; i < 448; i += 224) {
                int cl = i / 56, w = i % 56;
                const float* xc = xn + (g*8 + cl) * P_;
                float s = 0.f;
#pragma unroll
                for (int c8 = 0; c8 < 8; c8++)
                    s += xc[clin[w][c8]] * cwgt[w][c8];
                svals[cl][w] = s;
            }
            __syncthreads();
            // --- GEMM accumulate ---
#pragma unroll
            for (int cl = 0; cl < 8; cl++) {
                float v0 = svals[cl][tx], v1 = svals[cl][tx+28];
#pragma unroll
                for (int r = 0; r < 8; r++) {
                    float wv = wsm[ty*8 + r][cl];
                    acc[r][0] += wv * v0;
                    acc[r][1] += wv * v1;
                }
            }
            __syncthreads();
        }
    }
#pragma unroll
    for (int r = 0; r < 8; r++) {
        int o = ty*8 + r;
        int base = (n * C_ + o) * P_ + (d * H_ + h) * W_;
        g_y1[base + tx]      = acc[r][0];
        g_y1[base + tx + 28] = acc[r][1];
    }
}

// ---------------- BN statistics (deterministic, one block per channel) ----------------
__global__ void bnstats_kernel(int which) {
    const float* y = which ? g_y3 : g_y1;
    int c = blockIdx.x;
    int tid = threadIdx.x;
    float s = 0.f, s2 = 0.f;
    for (int n = 0; n < N_; n++) {
        const float* p = y + (n * C_ + c) * P_;
        for (int i = tid; i < P_; i += 256) {
            float v = p[i];
            s += v; s2 += v * v;
        }
    }
    __shared__ float rs[256], rq[256];
    rs[tid] = s; rq[tid] = s2;
    __syncthreads();
    for (int st = 128; st > 0; st >>= 1) {
        if (tid < st) { rs[tid] += rs[tid+st]; rq[tid] += rq[tid+st]; }
        __syncthreads();
    }
    if (tid == 0) {
        float cnt = (float)(N_ * P_);
        float m = rs[0] / cnt;
        float var = rq[0] / cnt - m * m;
        g_stats[which*128 + c]      = m;
        g_stats[which*128 + 64 + c] = rsqrtf(var + 1e-5f);
    }
}

// ---------------- BN1 apply + relu -> padded buffer for conv2 ----------------
__global__ void bnrelu_kernel(const float* __restrict__ gamma, const float* __restrict__ beta) {
    int idx = blockIdx.x * 256 + threadIdx.x;
    if (idx >= N_*C_*P_) return;
    int c = (idx / P_) % C_;
    float m = g_stats[c], is = g_stats[64 + c];
    float v = (g_y1[idx] - m) * is * gamma[c] + beta[c];
    v = fmaxf(v, 0.f);
    int pp = idx % P_;
    int w = pp % W_, hh = (pp / W_) % H_, dd = pp / (W_*H_);
    int nc = idx / P_;
    g_y2pad[nc * PPAD_ + (dd+1) * (HP_*WP_) + (hh+1) * WP_ + (w+1)] = v;
}

// ---------------- kernel 5: conv2 64 -> 64, 3x3x3 ----------------
__global__ __launch_bounds__(224) void conv2_kernel(const float* __restrict__ w2,
                                                    const float* __restrict__ b2) {
    int ndh = blockIdx.x;
    int h = ndh % H_;
    int d = (ndh / H_) % D_;
    int n = ndh / (D_*H_);
    int tx = threadIdx.x;
    int ty = threadIdx.y;
    int tid = ty * 28 + tx;

    __shared__ float xrow[58];
    __shared__ float wsm[64*3];

    float acc[8][2];
#pragma unroll
    for (int r = 0; r < 8; r++) { acc[r][0] = 0.f; acc[r][1] = 0.f; }

    const float* xp = g_y2pad + n * (C_*PPAD_);

    for (int ci = 0; ci < C_; ci++) {
#pragma unroll
        for (int kd = 0; kd < 3; kd++) {
#pragma unroll
            for (int kh = 0; kh < 3; kh++) {
                const float* src = xp + ci * PPAD_ + (d + kd) * (HP_*WP_) + (h + kh) * WP_;
                if (tid < 58) xrow[tid] = src[tid];
                if (tid < 192) {
                    int co = tid / 3, kw = tid % 3;
                    wsm[tid] = w2[(co * C_ + ci) * 27 + kd*9 + kh*3 + kw];
                }
                __syncthreads();
                float xa0 = xrow[tx],    xa1 = xrow[tx+1],  xa2 = xrow[tx+2];
                float xb0 = xrow[tx+28], xb1 = xrow[tx+29], xb2 = xrow[tx+30];
#pragma unroll
                for (int r = 0; r < 8; r++) {
                    int co = ty * 8 + r;
                    float v0 = wsm[co*3], v1 = wsm[co*3+1], v2 = wsm[co*3+2];
                    acc[r][0] += v0*xa0 + v1*xa1 + v2*xa2;
                    acc[r][1] += v0*xb0 + v1*xb1 + v2*xb2;
                }
                __syncthreads();
            }
        }
    }
#pragma unroll
    for (int r = 0; r < 8; r++) {
        int co = ty*8 + r;
        float b = b2[co];
        int base = (n * C_ + co) * P_ + (d * H_ + h) * W_;
        g_y3[base + tx]      = acc[r][0] + b;
        g_y3[base + tx + 28] = acc[r][1] + b;
    }
}

// ---------------- final: bn2 + residual + relu ----------------
__global__ void final_kernel(const float* __restrict__ x,
                             const float* __restrict__ gamma2,
                             const float* __restrict__ beta2,
                             float* __restrict__ out) {
    int idx = blockIdx.x * 256 + threadIdx.x;
    if (idx >= N_*C_*P_) return;
    int c = (idx / P_) % C_;
    float m = g_stats[128 + c], is = g_stats[192 + c];
    float v = (g_y3[idx] - m) * is * gamma2[c] + beta2[c] + x[idx];
    out[idx] = fmaxf(v, 0.f);
}

// ---------------- launcher ----------------
extern "C" void kernel_launch(void* const* d_in, const int* in_sizes, int n_in,
                              void* d_out, int out_size) {
    const float* x      = (const float*)d_in[0];
    const float* w_off  = (const float*)d_in[1];
    const float* b_off  = (const float*)d_in[2];
    const float* w1     = (const float*)d_in[3];
    const float* gamma1 = (const float*)d_in[4];
    const float* beta1  = (const float*)d_in[5];
    const float* w2     = (const float*)d_in[6];
    const float* b2     = (const float*)d_in[7];
    const float* gamma2 = (const float*)d_in[8];
    const float* beta2  = (const float*)d_in[9];
    float* out = (float*)d_out;

    dim3 blk(28, 8);
    int padtot = N_*C_*PPAD_;
    int tot = N_*C_*P_;

    padinit_kernel<<<(padtot + 255) / 256, 256>>>(x);
    offconv_kernel<<<dim3(N_*D_*H_, 9), blk>>>(w_off, b_off);
    deform_kernel<<<N_*D_*H_, blk>>>(x, w1);
    bnstats_kernel<<<64, 256>>>(0);
    bnrelu_kernel<<<(tot + 255) / 256, 256>>>(gamma1, beta1);
    conv2_kernel<<<N_*D_*H_, blk>>>(w2, b2);
    bnstats_kernel<<<64, 256>>>(1);
    final_kernel<<<(tot + 255) / 256, 256>>>(x, gamma2, beta2, out);
}

// round 2
// speedup vs baseline: 2.3395x; 2.3395x over previous
#include <cuda_runtime.h>
#include <cstdint>

#define N_ 2
#define C_ 64
#define D_ 8
#define H_ 56
#define W_ 56
#define G_ 8
#define K_ 27
#define CO_OFF 648
#define P_ (D_*H_*W_)          // 25088
#define DP_ (D_+2)
#define HP_ (H_+2)
#define WP_ (W_+2)
#define PPAD_ (DP_*HP_*WP_)    // 33640
#define HPWP_ (HP_*WP_)

// ---------------- scratch (no allocation allowed) ----------------
__device__ float g_xpad[N_*C_*PPAD_];    // padded input for offset conv
__device__ float g_y2pad[N_*C_*PPAD_];   // padded bn1+relu output for conv2
__device__ float g_off[N_*CO_OFF*P_];    // offset tensor (130 MB)
__device__ float g_y1[N_*C_*P_];         // deform conv output
__device__ float g_y3[N_*C_*P_];         // conv2 output
__device__ float g_stats[4*C_];          // mean1, istd1, mean2, istd2

// ---------------- helpers ----------------
__device__ __forceinline__ uint32_t f2tf32(float x) {
    uint32_t r;
    asm("cvt.rna.tf32.f32 %0, %1;" : "=r"(r) : "f"(x));
    return r;
}

__device__ __forceinline__ void mma_tf32(float c[4], const uint32_t a[4],
                                         uint32_t b0, uint32_t b1) {
    asm volatile(
        "mma.sync.aligned.m16n8k8.row.col.f32.tf32.tf32.f32 "
        "{%0,%1,%2,%3}, {%4,%5,%6,%7}, {%8,%9}, {%0,%1,%2,%3};"
        : "+f"(c[0]), "+f"(c[1]), "+f"(c[2]), "+f"(c[3])
        : "r"(a[0]), "r"(a[1]), "r"(a[2]), "r"(a[3]), "r"(b0), "r"(b1));
}

// ---------------- kernel 0: build padded x, zero pad edges of y2pad ----------------
__global__ void padinit_kernel(const float* __restrict__ x) {
    int idx = blockIdx.x * 256 + threadIdx.x;
    if (idx >= N_*C_*PPAD_) return;
    int wp = idx % WP_;
    int hp = (idx / WP_) % HP_;
    int dp = (idx / (WP_*HP_)) % DP_;
    int nc = idx / PPAD_;
    bool interior = (dp >= 1 && dp <= D_ && hp >= 1 && hp <= H_ && wp >= 1 && wp <= W_);
    float v = 0.f;
    if (interior)
        v = x[nc * P_ + (dp-1) * (H_*W_) + (hp-1) * W_ + (wp-1)];
    g_xpad[idx] = v;
    if (!interior) g_y2pad[idx] = 0.f;
}

// ---------------- kernel 1: offset conv as tf32 tensor-core implicit GEMM ----------
// GEMM: out[co, p] = sum_{ci, tap} W[co, ci*27+tap] * X[ci*27+tap, p]
// Block: BM=64 co  x  BN=112 positions (row pair h, h+1 of one (n,d)).
// K-chunk = 1 input channel, taps padded 27->32 (zero weights), 4 ksteps of 8.
// Warp grid 2(M) x 2(N): warp computes 32 co x 56 positions.
// grid: (448, 11)  block: 128
__global__ __launch_bounds__(128) void offconv_mma_kernel(const float* __restrict__ w_off,
                                                          const float* __restrict__ b_off) {
    __shared__ float Ws[64*36];     // weights [co][32k], stride 36 (conflict-free A loads)
    __shared__ float slab[696];     // xpad slab [kd 3][hh 4][ww 58] (tf32-rounded)
    __shared__ int   lut[32];       // tap -> slab base offset

    int bx = blockIdx.x;
    int hp = bx % 28;
    int h  = hp * 2;
    int d  = (bx / 28) % D_;
    int n  = bx / (28 * D_);
    int cot = blockIdx.y;           // co tile: 64 channels, 11 tiles cover 648 (pad 704)

    int tid  = threadIdx.x;
    int lane = tid & 31, warp = tid >> 5;
    int gid  = lane >> 2, tg = lane & 3;   // group-id (0..7), thread-in-group (0..3)
    int mw   = warp >> 1, nw = warp & 1;   // warp M/N coords

    if (tid < 32) {
        int j = tid, base = 0;
        if (j < 27) {
            int kd = j / 9, kh = (j / 3) % 3, kw = j % 3;
            base = kd * 232 + kh * 58 + kw;   // 232 = 4*58
        }
        lut[j] = base;
    }

    float c[2][7][4];
#pragma unroll
    for (int mt = 0; mt < 2; mt++)
#pragma unroll
        for (int nt = 0; nt < 7; nt++)
#pragma unroll
            for (int i = 0; i < 4; i++) c[mt][nt][i] = 0.f;

    const float* xp = g_xpad + n * (C_*PPAD_) + d * HPWP_ + h * WP_;

    for (int ci = 0; ci < C_; ci++) {
        __syncthreads();
        // stage weights: Ws[co][j] = w_off[cot*64+co][ci*27 + j], j<27, else 0
        const float* wsrc = w_off + (size_t)ci * 27;
#pragma unroll 4
        for (int i = tid; i < 2048; i += 128) {
            int co = i >> 5, j = i & 31;
            int cog = cot * 64 + co;
            float v = 0.f;
            if (j < 27 && cog < CO_OFF) v = wsrc[(size_t)cog * 1728 + j];
            Ws[co * 36 + j] = __uint_as_float(f2tf32(v));
        }
        // stage xpad slab for this ci: [kd][hh][ww] (3 x 4 x 58)
        const float* src = xp + (size_t)ci * PPAD_;
#pragma unroll
        for (int i = tid; i < 696; i += 128) {
            int kd = i / 232;
            int r2 = i - kd * 232;
            int hh = r2 / 58;
            int ww = r2 - hh * 58;
            slab[i] = __uint_as_float(f2tf32(src[kd * HPWP_ + hh * WP_ + ww]));
        }
        __syncthreads();

#pragma unroll
        for (int ks = 0; ks < 4; ks++) {
            int l0 = lut[ks * 8 + tg];
            int l1 = lut[ks * 8 + tg + 4];
            uint32_t a[2][4];
#pragma unroll
            for (int mt = 0; mt < 2; mt++) {
                const float* wr = &Ws[(mw * 32 + mt * 16 + gid) * 36 + ks * 8 + tg];
                a[mt][0] = __float_as_uint(wr[0]);
                a[mt][1] = __float_as_uint(wr[8 * 36]);
                a[mt][2] = __float_as_uint(wr[4]);
                a[mt][3] = __float_as_uint(wr[8 * 36 + 4]);
            }
            int ro = nw * 58 + gid;
#pragma unroll
            for (int nt = 0; nt < 7; nt++) {
                uint32_t b0 = __float_as_uint(slab[l0 + ro]);
                uint32_t b1 = __float_as_uint(slab[l1 + ro]);
                mma_tf32(c[0][nt], a[0], b0, b1);
                mma_tf32(c[1][nt], a[1], b0, b1);
                ro += 8;
            }
        }
    }

    // store: warp (mw,nw), rows co = cot*64 + mw*32 + mt*16 + gid (+8), cols nw*56 + nt*8 + tg*2 (+1)
    int hrow = h + nw;
    int pbase = (d * H_ + hrow) * W_;
#pragma unroll
    for (int mt = 0; mt < 2; mt++) {
        int co0 = cot * 64 + mw * 32 + mt * 16 + gid;
#pragma unroll
        for (int half = 0; half < 2; half++) {
            int co = co0 + half * 8;
            if (co < CO_OFF) {
                float bo = b_off[co];
                float* outp = g_off + ((size_t)(n * CO_OFF + co)) * P_ + pbase;
#pragma unroll
                for (int nt = 0; nt < 7; nt++) {
                    int w0 = nt * 8 + tg * 2;
                    outp[w0]     = c[mt][nt][half * 2 + 0] + bo;
                    outp[w0 + 1] = c[mt][nt][half * 2 + 1] + bo;
                }
            }
        }
    }
}

// ---------------- kernel 2: deformable conv (sample + GEMM) ----------------
// grid: N*D*H   block: (28, 8)
__global__ __launch_bounds__(224) void deform_kernel(const float* __restrict__ x,
                                                     const float* __restrict__ w1) {
    int ndh = blockIdx.x;
    int h = ndh % H_;
    int d = (ndh / H_) % D_;
    int n = ndh / (D_*H_);
    int tx = threadIdx.x;
    int ty = threadIdx.y;
    int tid = ty * 28 + tx;

    __shared__ float svals[8][56];
    __shared__ float wsm[64][9];     // padded stride 9 (bank conflicts)
    __shared__ int   clin[56][9];
    __shared__ float cwgt[56][9];

    float acc[8][2];
#pragma unroll
    for (int r = 0; r < 8; r++) { acc[r][0] = 0.f; acc[r][1] = 0.f; }

    const float* xn = x + n * (C_*P_);

    for (int g = 0; g < G_; g++) {
        for (int k = 0; k < K_; k++) {
            // --- corner index/weight computation: one thread per w position ---
            if (tid < 56) {
                int w = tid;
                int kd = k / 9, kh = (k / 3) % 3, kw = k % 3;
                int obase = (n * CO_OFF + (g*K_ + k) * 3) * P_ + (d * H_ + h) * W_ + w;
                float od = g_off[obase];
                float oh = g_off[obase + P_];
                float ow = g_off[obase + 2*P_];
                float pd = (float)(d + kd - 1) + od;
                float ph = (float)(h + kh - 1) + oh;
                float pw = (float)(w + kw - 1) + ow;
                float d0f = floorf(pd), h0f = floorf(ph), w0f = floorf(pw);
                float fd = pd - d0f, fh = ph - h0f, fw = pw - w0f;
                int d0 = (int)d0f, h0 = (int)h0f, w0 = (int)w0f;
#pragma unroll
                for (int c8 = 0; c8 < 8; c8++) {
                    int cd = c8 >> 2, ch = (c8 >> 1) & 1, cw = c8 & 1;
                    int id = d0 + cd, ih = h0 + ch, iw = w0 + cw;
                    float wt = (cd ? fd : 1.f - fd) * (ch ? fh : 1.f - fh) * (cw ? fw : 1.f - fw);
                    bool valid = (id >= 0 && id < D_ && ih >= 0 && ih < H_ && iw >= 0 && iw < W_);
                    int idc = min(max(id, 0), D_-1);
                    int ihc = min(max(ih, 0), H_-1);
                    int iwc = min(max(iw, 0), W_-1);
                    clin[w][c8] = (idc * H_ + ihc) * W_ + iwc;
                    cwgt[w][c8] = valid ? wt : 0.f;
                }
            }
            // --- load weight slice w1[o][g*8+cl][k] ---
            for (int i = tid; i < 512; i += 224) {
                int o = i >> 3, cl = i & 7;
                wsm[o][cl] = w1[(o * C_ + g*8 + cl) * K_ + k];
            }
            __syncthreads();
            // --- trilinear sampling: 448 values ---
            for (int i = tid; i < 448; i += 224) {
                int cl = i / 56, w = i % 56;
                const float* xc = xn + (g*8 + cl) * P_;
                float s = 0.f;
#pragma unroll
                for (int c8 = 0; c8 < 8; c8++)
                    s += xc[clin[w][c8]] * cwgt[w][c8];
                svals[cl][w] = s;
            }
            __syncthreads();
            // --- GEMM accumulate ---
#pragma unroll
            for (int cl = 0; cl < 8; cl++) {
                float v0 = svals[cl][tx], v1 = svals[cl][tx+28];
#pragma unroll
                for (int r = 0; r < 8; r++) {
                    float wv = wsm[ty*8 + r][cl];
                    acc[r][0] += wv * v0;
                    acc[r][1] += wv * v1;
                }
            }
            __syncthreads();
        }
    }
#pragma unroll
    for (int r = 0; r < 8; r++) {
        int o = ty*8 + r;
        int base = (n * C_ + o) * P_ + (d * H_ + h) * W_;
        g_y1[base + tx]      = acc[r][0];
        g_y1[base + tx + 28] = acc[r][1];
    }
}

// ---------------- BN statistics (deterministic, one block per channel) ----------------
__global__ void bnstats_kernel(int which) {
    const float* y = which ? g_y3 : g_y1;
    int c = blockIdx.x;
    int tid = threadIdx.x;
    float s = 0.f, s2 = 0.f;
    for (int n = 0; n < N_; n++) {
        const float* p = y + (n * C_ + c) * P_;
        for (int i = tid; i < P_; i += 256) {
            float v = p[i];
            s += v; s2 += v * v;
        }
    }
    __shared__ float rs[256], rq[256];
    rs[tid] = s; rq[tid] = s2;
    __syncthreads();
    for (int st = 128; st > 0; st >>= 1) {
        if (tid < st) { rs[tid] += rs[tid+st]; rq[tid] += rq[tid+st]; }
        __syncthreads();
    }
    if (tid == 0) {
        float cnt = (float)(N_ * P_);
        float m = rs[0] / cnt;
        float var = rq[0] / cnt - m * m;
        g_stats[which*128 + c]      = m;
        g_stats[which*128 + 64 + c] = rsqrtf(var + 1e-5f);
    }
}

// ---------------- BN1 apply + relu -> padded buffer for conv2 ----------------
__global__ void bnrelu_kernel(const float* __restrict__ gamma, const float* __restrict__ beta) {
    int idx = blockIdx.x * 256 + threadIdx.x;
    if (idx >= N_*C_*P_) return;
    int c = (idx / P_) % C_;
    float m = g_stats[c], is = g_stats[64 + c];
    float v = (g_y1[idx] - m) * is * gamma[c] + beta[c];
    v = fmaxf(v, 0.f);
    int pp = idx % P_;
    int w = pp % W_, hh = (pp / W_) % H_, dd = pp / (W_*H_);
    int nc = idx / P_;
    g_y2pad[nc * PPAD_ + (dd+1) * (HP_*WP_) + (hh+1) * WP_ + (w+1)] = v;
}

// ---------------- kernel 5: conv2 64 -> 64, 3x3x3 ----------------
__global__ __launch_bounds__(224) void conv2_kernel(const float* __restrict__ w2,
                                                    const float* __restrict__ b2) {
    int ndh = blockIdx.x;
    int h = ndh % H_;
    int d = (ndh / H_) % D_;
    int n = ndh / (D_*H_);
    int tx = threadIdx.x;
    int ty = threadIdx.y;
    int tid = ty * 28 + tx;

    __shared__ float xrow[58];
    __shared__ float wsm[64*3];

    float acc[8][2];
#pragma unroll
    for (int r = 0; r < 8; r++) { acc[r][0] = 0.f; acc[r][1] = 0.f; }

    const float* xp = g_y2pad + n * (C_*PPAD_);

    for (int ci = 0; ci < C_; ci++) {
#pragma unroll
        for (int kd = 0; kd < 3; kd++) {
#pragma unroll
            for (int kh = 0; kh < 3; kh++) {
                const float* src = xp + ci * PPAD_ + (d + kd) * (HP_*WP_) + (h + kh) * WP_;
                if (tid < 58) xrow[tid] = src[tid];
                if (tid < 192) {
                    int co = tid / 3, kw = tid % 3;
                    wsm[tid] = w2[(co * C_ + ci) * 27 + kd*9 + kh*3 + kw];
                }
                __syncthreads();
                float xa0 = xrow[tx],    xa1 = xrow[tx+1],  xa2 = xrow[tx+2];
                float xb0 = xrow[tx+28], xb1 = xrow[tx+29], xb2 = xrow[tx+30];
#pragma unroll
                for (int r = 0; r < 8; r++) {
                    int co = ty * 8 + r;
                    float v0 = wsm[co*3], v1 = wsm[co*3+1], v2 = wsm[co*3+2];
                    acc[r][0] += v0*xa0 + v1*xa1 + v2*xa2;
                    acc[r][1] += v0*xb0 + v1*xb1 + v2*xb2;
                }
                __syncthreads();
            }
        }
    }
#pragma unroll
    for (int r = 0; r < 8; r++) {
        int co = ty*8 + r;
        float b = b2[co];
        int base = (n * C_ + co) * P_ + (d * H_ + h) * W_;
        g_y3[base + tx]      = acc[r][0] + b;
        g_y3[base + tx + 28] = acc[r][1] + b;
    }
}

// ---------------- final: bn2 + residual + relu ----------------
__global__ void final_kernel(const float* __restrict__ x,
                             const float* __restrict__ gamma2,
                             const float* __restrict__ beta2,
                             float* __restrict__ out) {
    int idx = blockIdx.x * 256 + threadIdx.x;
    if (idx >= N_*C_*P_) return;
    int c = (idx / P_) % C_;
    float m = g_stats[128 + c], is = g_stats[192 + c];
    float v = (g_y3[idx] - m) * is * gamma2[c] + beta2[c] + x[idx];
    out[idx] = fmaxf(v, 0.f);
}

// ---------------- launcher ----------------
extern "C" void kernel_launch(void* const* d_in, const int* in_sizes, int n_in,
                              void* d_out, int out_size) {
    const float* x      = (const float*)d_in[0];
    const float* w_off  = (const float*)d_in[1];
    const float* b_off  = (const float*)d_in[2];
    const float* w1     = (const float*)d_in[3];
    const float* gamma1 = (const float*)d_in[4];
    const float* beta1  = (const float*)d_in[5];
    const float* w2     = (const float*)d_in[6];
    const float* b2     = (const float*)d_in[7];
    const float* gamma2 = (const float*)d_in[8];
    const float* beta2  = (const float*)d_in[9];
    float* out = (float*)d_out;

    dim3 blk(28, 8);
    int padtot = N_*C_*PPAD_;
    int tot = N_*C_*P_;

    padinit_kernel<<<(padtot + 255) / 256, 256>>>(x);
    offconv_mma_kernel<<<dim3(448, 11), 128>>>(w_off, b_off);
    deform_kernel<<<N_*D_*H_, blk>>>(x, w1);
    bnstats_kernel<<<64, 256>>>(0);
    bnrelu_kernel<<<(tot + 255) / 256, 256>>>(gamma1, beta1);
    conv2_kernel<<<N_*D_*H_, blk>>>(w2, b2);
    bnstats_kernel<<<64, 256>>>(1);
    final_kernel<<<(tot + 255) / 256, 256>>>(x, gamma2, beta2, out);
}

// round 3
// speedup vs baseline: 2.6663x; 1.1397x over previous
#include <cuda_runtime.h>
#include <cstdint>

#define N_ 2
#define C_ 64
#define D_ 8
#define H_ 56
#define W_ 56
#define G_ 8
#define K_ 27
#define CO_OFF 648
#define P_ (D_*H_*W_)          // 25088
#define DP_ (D_+2)
#define HP_ (H_+2)
#define WP_ (W_+2)
#define PPAD_ (DP_*HP_*WP_)    // 33640
#define HPWP_ (HP_*WP_)

// ---------------- scratch (no allocation allowed) ----------------
__device__ float g_xpad[N_*C_*PPAD_];    // padded input for offset conv
__device__ float g_y2pad[N_*C_*PPAD_];   // padded bn1+relu output for conv2
__device__ float g_off[N_*CO_OFF*P_];    // offset tensor (130 MB)
__device__ float g_y1[N_*C_*P_];         // deform conv output
__device__ float g_y3[N_*C_*P_];         // conv2 output
__device__ float g_stats[4*C_];          // mean1, istd1, mean2, istd2

// ---------------- helpers ----------------
__device__ __forceinline__ uint32_t f2tf32(float x) {
    uint32_t r;
    asm("cvt.rna.tf32.f32 %0, %1;" : "=r"(r) : "f"(x));
    return r;
}

__device__ __forceinline__ void mma_tf32(float c[4], const uint32_t a[4],
                                         uint32_t b0, uint32_t b1) {
    asm volatile(
        "mma.sync.aligned.m16n8k8.row.col.f32.tf32.tf32.f32 "
        "{%0,%1,%2,%3}, {%4,%5,%6,%7}, {%8,%9}, {%0,%1,%2,%3};"
        : "+f"(c[0]), "+f"(c[1]), "+f"(c[2]), "+f"(c[3])
        : "r"(a[0]), "r"(a[1]), "r"(a[2]), "r"(a[3]), "r"(b0), "r"(b1));
}

// ---------------- kernel 0: build padded x, zero pad edges of y2pad ----------------
__global__ void padinit_kernel(const float* __restrict__ x) {
    int idx = blockIdx.x * 256 + threadIdx.x;
    if (idx >= N_*C_*PPAD_) return;
    int wp = idx % WP_;
    int hp = (idx / WP_) % HP_;
    int dp = (idx / (WP_*HP_)) % DP_;
    int nc = idx / PPAD_;
    bool interior = (dp >= 1 && dp <= D_ && hp >= 1 && hp <= H_ && wp >= 1 && wp <= W_);
    float v = 0.f;
    if (interior)
        v = x[nc * P_ + (dp-1) * (H_*W_) + (hp-1) * W_ + (wp-1)];
    g_xpad[idx] = v;
    if (!interior) g_y2pad[idx] = 0.f;
}

// ---------------- kernel 1: offset conv as tf32 implicit GEMM ----------
// BM=64 co x BN=224 positions (4 rows h..h+3 of one (n,d)). 256 thr, warps 2M x 4N.
// grid: (224, 11)
__global__ __launch_bounds__(256) void offconv_mma_kernel(const float* __restrict__ w_off,
                                                          const float* __restrict__ b_off) {
    __shared__ float Ws[64*36];     // weights [co][32k], stride 36
    __shared__ float slab[1044];    // xpad slab [kd 3][hh 6][ww 58]
    __shared__ int   lut[32];       // tap -> slab base offset

    int bx = blockIdx.x;
    int hq = bx % 14;
    int h  = hq * 4;
    int d  = (bx / 14) % D_;
    int n  = bx / (14 * D_);
    int cot = blockIdx.y;

    int tid  = threadIdx.x;
    int lane = tid & 31, warp = tid >> 5;
    int gid  = lane >> 2, tg = lane & 3;
    int mw   = warp >> 2, nw = warp & 3;

    if (tid < 32) {
        int j = tid, base = 0;
        if (j < 27) {
            int kd = j / 9, kh = (j / 3) % 3, kw = j % 3;
            base = kd * 348 + kh * 58 + kw;   // 348 = 6*58
        }
        lut[j] = base;
    }

    float c[2][7][4];
#pragma unroll
    for (int mt = 0; mt < 2; mt++)
#pragma unroll
        for (int nt = 0; nt < 7; nt++)
#pragma unroll
            for (int i = 0; i < 4; i++) c[mt][nt][i] = 0.f;

    const float* xp = g_xpad + n * (C_*PPAD_) + d * HPWP_ + h * WP_;

    for (int ci = 0; ci < C_; ci++) {
        __syncthreads();
        const float* wsrc = w_off + (size_t)ci * 27;
#pragma unroll
        for (int i = tid; i < 2048; i += 256) {
            int co = i >> 5, j = i & 31;
            int cog = cot * 64 + co;
            float v = 0.f;
            if (j < 27 && cog < CO_OFF) v = wsrc[(size_t)cog * 1728 + j];
            Ws[co * 36 + j] = __uint_as_float(f2tf32(v));
        }
        const float* src = xp + (size_t)ci * PPAD_;
#pragma unroll
        for (int i = tid; i < 1044; i += 256) {
            int kd = i / 348;
            int r2 = i - kd * 348;
            int hh = r2 / 58;
            int ww = r2 - hh * 58;
            slab[i] = __uint_as_float(f2tf32(src[kd * HPWP_ + hh * WP_ + ww]));
        }
        __syncthreads();

#pragma unroll
        for (int ks = 0; ks < 4; ks++) {
            int l0 = lut[ks * 8 + tg];
            int l1 = lut[ks * 8 + tg + 4];
            uint32_t a[2][4];
#pragma unroll
            for (int mt = 0; mt < 2; mt++) {
                const float* wr = &Ws[(mw * 32 + mt * 16 + gid) * 36 + ks * 8 + tg];
                a[mt][0] = __float_as_uint(wr[0]);
                a[mt][1] = __float_as_uint(wr[8 * 36]);
                a[mt][2] = __float_as_uint(wr[4]);
                a[mt][3] = __float_as_uint(wr[8 * 36 + 4]);
            }
            int ro = nw * 58 + gid;
#pragma unroll
            for (int nt = 0; nt < 7; nt++) {
                uint32_t b0 = __float_as_uint(slab[l0 + ro]);
                uint32_t b1 = __float_as_uint(slab[l1 + ro]);
                mma_tf32(c[0][nt], a[0], b0, b1);
                mma_tf32(c[1][nt], a[1], b0, b1);
                ro += 8;
            }
        }
    }

    int hrow = h + nw;
    int pbase = (d * H_ + hrow) * W_;
#pragma unroll
    for (int mt = 0; mt < 2; mt++) {
        int co0 = cot * 64 + mw * 32 + mt * 16 + gid;
#pragma unroll
        for (int half = 0; half < 2; half++) {
            int co = co0 + half * 8;
            if (co < CO_OFF) {
                float bo = b_off[co];
                float* outp = g_off + ((size_t)(n * CO_OFF + co)) * P_ + pbase;
#pragma unroll
                for (int nt = 0; nt < 7; nt++) {
                    int w0 = nt * 8 + tg * 2;
                    outp[w0]     = c[mt][nt][half * 2 + 0] + bo;
                    outp[w0 + 1] = c[mt][nt][half * 2 + 1] + bo;
                }
            }
        }
    }
}

// ---------------- kernel 2: deformable conv (pipelined sample + GEMM) ----------------
// grid: N*D*H   block: (28, 8)
__global__ __launch_bounds__(224) void deform_kernel(const float* __restrict__ x,
                                                     const float* __restrict__ w1) {
    int ndh = blockIdx.x;
    int h = ndh % H_;
    int d = (ndh / H_) % D_;
    int n = ndh / (D_*H_);
    int tx = threadIdx.x;
    int ty = threadIdx.y;
    int tid = ty * 28 + tx;

    __shared__ float svals[8][56];
    __shared__ float wsm[2][64][9];
    __shared__ int   clin[2][56][9];
    __shared__ float cwgt[2][56][9];

    float acc[8][2];
#pragma unroll
    for (int r = 0; r < 8; r++) { acc[r][0] = 0.f; acc[r][1] = 0.f; }

    const float* xn = x + n * (C_*P_);

    // phaseA: threads 0-55 compute corner indices/weights; threads 56-223 stage w1 slice
    auto phaseA = [&](int t, int buf) {
        int g = t / 27, k = t - g * 27;
        if (tid < 56) {
            int w = tid;
            int kd = k / 9, kh = (k / 3) % 3, kw = k % 3;
            int obase = (n * CO_OFF + (g*K_ + k) * 3) * P_ + (d * H_ + h) * W_ + w;
            float od = __ldg(&g_off[obase]);
            float oh = __ldg(&g_off[obase + P_]);
            float ow = __ldg(&g_off[obase + 2*P_]);
            float pd = (float)(d + kd - 1) + od;
            float ph = (float)(h + kh - 1) + oh;
            float pw = (float)(w + kw - 1) + ow;
            float d0f = floorf(pd), h0f = floorf(ph), w0f = floorf(pw);
            float fd = pd - d0f, fh = ph - h0f, fw = pw - w0f;
            int d0 = (int)d0f, h0 = (int)h0f, w0 = (int)w0f;
#pragma unroll
            for (int c8 = 0; c8 < 8; c8++) {
                int cd = c8 >> 2, ch = (c8 >> 1) & 1, cw = c8 & 1;
                int id = d0 + cd, ih = h0 + ch, iw = w0 + cw;
                float wt = (cd ? fd : 1.f - fd) * (ch ? fh : 1.f - fh) * (cw ? fw : 1.f - fw);
                bool valid = (id >= 0 && id < D_ && ih >= 0 && ih < H_ && iw >= 0 && iw < W_);
                int idc = min(max(id, 0), D_-1);
                int ihc = min(max(ih, 0), H_-1);
                int iwc = min(max(iw, 0), W_-1);
                clin[buf][w][c8] = (idc * H_ + ihc) * W_ + iwc;
                cwgt[buf][w][c8] = valid ? wt : 0.f;
            }
        } else {
            for (int i = tid - 56; i < 512; i += 168) {
                int o = i >> 3, cl = i & 7;
                wsm[buf][o][cl] = __ldg(&w1[(o * C_ + g*8 + cl) * K_ + k]);
            }
        }
    };

    phaseA(0, 0);
    __syncthreads();

    for (int t = 0; t < 216; t++) {
        int buf = t & 1;
        int g = t / 27;
        // --- trilinear sampling ---
#pragma unroll
        for (int rep = 0; rep < 2; rep++) {
            int i = tid + rep * 224;
            int cl = i / 56, w = i - cl * 56;
            const float* xc = xn + (g*8 + cl) * P_;
            float s = 0.f;
#pragma unroll
            for (int c8 = 0; c8 < 8; c8++)
                s += __ldg(&xc[clin[buf][w][c8]]) * cwgt[buf][w][c8];
            svals[cl][w] = s;
        }
        __syncthreads();
        // --- stage next tap (overlaps with GEMM below) ---
        if (t + 1 < 216) phaseA(t + 1, buf ^ 1);
        // --- GEMM accumulate ---
#pragma unroll
        for (int cl = 0; cl < 8; cl++) {
            float v0 = svals[cl][tx], v1 = svals[cl][tx+28];
#pragma unroll
            for (int r = 0; r < 8; r++) {
                float wv = wsm[buf][ty*8 + r][cl];
                acc[r][0] += wv * v0;
                acc[r][1] += wv * v1;
            }
        }
        __syncthreads();
    }
#pragma unroll
    for (int r = 0; r < 8; r++) {
        int o = ty*8 + r;
        int base = (n * C_ + o) * P_ + (d * H_ + h) * W_;
        g_y1[base + tx]      = acc[r][0];
        g_y1[base + tx + 28] = acc[r][1];
    }
}

// ---------------- BN statistics (deterministic, one block per channel) ----------------
__global__ void bnstats_kernel(int which) {
    const float* y = which ? g_y3 : g_y1;
    int c = blockIdx.x;
    int tid = threadIdx.x;
    float s = 0.f, s2 = 0.f;
    for (int n = 0; n < N_; n++) {
        const float* p = y + (n * C_ + c) * P_;
        for (int i = tid; i < P_; i += 256) {
            float v = p[i];
            s += v; s2 += v * v;
        }
    }
    __shared__ float rs[256], rq[256];
    rs[tid] = s; rq[tid] = s2;
    __syncthreads();
    for (int st = 128; st > 0; st >>= 1) {
        if (tid < st) { rs[tid] += rs[tid+st]; rq[tid] += rq[tid+st]; }
        __syncthreads();
    }
    if (tid == 0) {
        float cnt = (float)(N_ * P_);
        float m = rs[0] / cnt;
        float var = rq[0] / cnt - m * m;
        g_stats[which*128 + c]      = m;
        g_stats[which*128 + 64 + c] = rsqrtf(var + 1e-5f);
    }
}

// ---------------- BN1 apply + relu -> padded buffer for conv2 ----------------
__global__ void bnrelu_kernel(const float* __restrict__ gamma, const float* __restrict__ beta) {
    int idx = blockIdx.x * 256 + threadIdx.x;
    if (idx >= N_*C_*P_) return;
    int c = (idx / P_) % C_;
    float m = g_stats[c], is = g_stats[64 + c];
    float v = (g_y1[idx] - m) * is * gamma[c] + beta[c];
    v = fmaxf(v, 0.f);
    int pp = idx % P_;
    int w = pp % W_, hh = (pp / W_) % H_, dd = pp / (W_*H_);
    int nc = idx / P_;
    g_y2pad[nc * PPAD_ + (dd+1) * (HP_*WP_) + (hh+1) * WP_ + (w+1)] = v;
}

// ---------------- kernel 5: conv2 as 3xtf32 implicit GEMM (near-fp32 accuracy) -------
// BM=64 co x BN=224 positions. grid: 224, block 256.
__global__ __launch_bounds__(256) void conv2_mma_kernel(const float* __restrict__ w2,
                                                        const float* __restrict__ b2) {
    __shared__ float WsH[64*36];
    __shared__ float WsL[64*36];
    __shared__ float slabH[1044];
    __shared__ float slabL[1044];
    __shared__ int   lut[32];

    int bx = blockIdx.x;
    int hq = bx % 14;
    int h  = hq * 4;
    int d  = (bx / 14) % D_;
    int n  = bx / (14 * D_);

    int tid  = threadIdx.x;
    int lane = tid & 31, warp = tid >> 5;
    int gid  = lane >> 2, tg = lane & 3;
    int mw   = warp >> 2, nw = warp & 3;

    if (tid < 32) {
        int j = tid, base = 0;
        if (j < 27) {
            int kd = j / 9, kh = (j / 3) % 3, kw = j % 3;
            base = kd * 348 + kh * 58 + kw;
        }
        lut[j] = base;
    }

    float c[2][7][4];
#pragma unroll
    for (int mt = 0; mt < 2; mt++)
#pragma unroll
        for (int nt = 0; nt < 7; nt++)
#pragma unroll
            for (int i = 0; i < 4; i++) c[mt][nt][i] = 0.f;

    const float* xp = g_y2pad + n * (C_*PPAD_) + d * HPWP_ + h * WP_;

    for (int ci = 0; ci < C_; ci++) {
        __syncthreads();
        const float* wsrc = w2 + (size_t)ci * 27;
#pragma unroll
        for (int i = tid; i < 2048; i += 256) {
            int co = i >> 5, j = i & 31;
            float v = 0.f;
            if (j < 27) v = wsrc[(size_t)co * 1728 + j];
            uint32_t hi = f2tf32(v);
            float lo = v - __uint_as_float(hi);
            WsH[co * 36 + j] = __uint_as_float(hi);
            WsL[co * 36 + j] = __uint_as_float(f2tf32(lo));
        }
        const float* src = xp + (size_t)ci * PPAD_;
#pragma unroll
        for (int i = tid; i < 1044; i += 256) {
            int kd = i / 348;
            int r2 = i - kd * 348;
            int hh = r2 / 58;
            int ww = r2 - hh * 58;
            float v = src[kd * HPWP_ + hh * WP_ + ww];
            uint32_t hi = f2tf32(v);
            float lo = v - __uint_as_float(hi);
            slabH[i] = __uint_as_float(hi);
            slabL[i] = __uint_as_float(f2tf32(lo));
        }
        __syncthreads();

#pragma unroll
        for (int ks = 0; ks < 4; ks++) {
            int l0 = lut[ks * 8 + tg];
            int l1 = lut[ks * 8 + tg + 4];
            uint32_t aH[2][4], aL[2][4];
#pragma unroll
            for (int mt = 0; mt < 2; mt++) {
                int rbase = (mw * 32 + mt * 16 + gid) * 36 + ks * 8 + tg;
                aH[mt][0] = __float_as_uint(WsH[rbase]);
                aH[mt][1] = __float_as_uint(WsH[rbase + 8*36]);
                aH[mt][2] = __float_as_uint(WsH[rbase + 4]);
                aH[mt][3] = __float_as_uint(WsH[rbase + 8*36 + 4]);
                aL[mt][0] = __float_as_uint(WsL[rbase]);
                aL[mt][1] = __float_as_uint(WsL[rbase + 8*36]);
                aL[mt][2] = __float_as_uint(WsL[rbase + 4]);
                aL[mt][3] = __float_as_uint(WsL[rbase + 8*36 + 4]);
            }
            int ro = nw * 58 + gid;
#pragma unroll
            for (int nt = 0; nt < 7; nt++) {
                uint32_t bH0 = __float_as_uint(slabH[l0 + ro]);
                uint32_t bH1 = __float_as_uint(slabH[l1 + ro]);
                uint32_t bL0 = __float_as_uint(slabL[l0 + ro]);
                uint32_t bL1 = __float_as_uint(slabL[l1 + ro]);
#pragma unroll
                for (int mt = 0; mt < 2; mt++) {
                    mma_tf32(c[mt][nt], aH[mt], bH0, bH1);
                    mma_tf32(c[mt][nt], aH[mt], bL0, bL1);
                    mma_tf32(c[mt][nt], aL[mt], bH0, bH1);
                }
                ro += 8;
            }
        }
    }

    int hrow = h + nw;
    int pbase = (d * H_ + hrow) * W_;
#pragma unroll
    for (int mt = 0; mt < 2; mt++) {
        int co0 = mw * 32 + mt * 16 + gid;
#pragma unroll
        for (int half = 0; half < 2; half++) {
            int co = co0 + half * 8;
            float bo = b2[co];
            float* outp = g_y3 + ((size_t)(n * C_ + co)) * P_ + pbase;
#pragma unroll
            for (int nt = 0; nt < 7; nt++) {
                int w0 = nt * 8 + tg * 2;
                outp[w0]     = c[mt][nt][half * 2 + 0] + bo;
                outp[w0 + 1] = c[mt][nt][half * 2 + 1] + bo;
            }
        }
    }
}

// ---------------- final: bn2 + residual + relu ----------------
__global__ void final_kernel(const float* __restrict__ x,
                             const float* __restrict__ gamma2,
                             const float* __restrict__ beta2,
                             float* __restrict__ out) {
    int idx = blockIdx.x * 256 + threadIdx.x;
    if (idx >= N_*C_*P_) return;
    int c = (idx / P_) % C_;
    float m = g_stats[128 + c], is = g_stats[192 + c];
    float v = (g_y3[idx] - m) * is * gamma2[c] + beta2[c] + x[idx];
    out[idx] = fmaxf(v, 0.f);
}

// ---------------- launcher ----------------
extern "C" void kernel_launch(void* const* d_in, const int* in_sizes, int n_in,
                              void* d_out, int out_size) {
    const float* x      = (const float*)d_in[0];
    const float* w_off  = (const float*)d_in[1];
    const float* b_off  = (const float*)d_in[2];
    const float* w1     = (const float*)d_in[3];
    const float* gamma1 = (const float*)d_in[4];
    const float* beta1  = (const float*)d_in[5];
    const float* w2     = (const float*)d_in[6];
    const float* b2     = (const float*)d_in[7];
    const float* gamma2 = (const float*)d_in[8];
    const float* beta2  = (const float*)d_in[9];
    float* out = (float*)d_out;

    dim3 blk(28, 8);
    int padtot = N_*C_*PPAD_;
    int tot = N_*C_*P_;

    padinit_kernel<<<(padtot + 255) / 256, 256>>>(x);
    offconv_mma_kernel<<<dim3(224, 11), 256>>>(w_off, b_off);
    deform_kernel<<<N_*D_*H_, blk>>>(x, w1);
    bnstats_kernel<<<64, 256>>>(0);
    bnrelu_kernel<<<(tot + 255) / 256, 256>>>(gamma1, beta1);
    conv2_mma_kernel<<<224, 256>>>(w2, b2);
    bnstats_kernel<<<64, 256>>>(1);
    final_kernel<<<(tot + 255) / 256, 256>>>(x, gamma2, beta2, out);
}